// round 13
// baseline (speedup 1.0000x reference)
#include <cuda_runtime.h>
#include <cuda_bf16.h>
#include <climits>

// GraphGather / segment_sum, single kernel, no init pass, no global atomics:
//   out[b, :] = sum of feats[a, :] for membership[a] == b
// feats: [524288, 128] f32, membership: [524288] i32 (SORTED), out: [16384, 128] f32.
//
// R13: CTA per 8 consecutive segments.
//  - warp 0: one 32-ary ballot lower_bound(chunk_begin) per CTA (amortized
//    8x vs per-warp search; hidden behind smem zeroing + syncthreads).
//  - 8 warps stream the chunk's rows (~256 +/- 16, CV 6%) in strided 32-row
//    batches: R6 body (8-deep unconditional/predicated float4 loads,
//    register carry, shfl'd membership), scan self-terminates when
//    membership leaves the chunk.
//  - segment flushes -> SHARED atomics (4KB s_acc, off the L2 path).
//  - one syncthreads, then one coalesced STG.128 pass writes all 8 segments:
//    plain stores overwrite the poisoned output, empty segments get zeros,
//    idempotent across graph replays. rel_err = 0 (exact FP grouping).

#define N_FEAT 128
#define FEAT4 (N_FEAT / 4)     // 32 float4 per row
#define SEGS 8                 // segments per CTA
#define TPB 256

__global__ __launch_bounds__(TPB)
void gg_fused_kernel(const float4* __restrict__ feats,
                     const int* __restrict__ memb,
                     float4* __restrict__ out,
                     int n_atoms, int batch) {
    __shared__ float s_acc[SEGS][N_FEAT];   // 4 KB
    __shared__ int s_start;

    const int tid = threadIdx.x;
    const int wid = tid >> 5;
    const int lane = tid & 31;
    const unsigned FULL = 0xFFFFFFFFu;

    const int chunk0 = blockIdx.x * SEGS;
    const int chunk_end = min(chunk0 + SEGS, batch);

    // Zero shared accumulators: 256 threads x one float4 = 4 KB exactly.
    ((float4*)s_acc)[tid] = make_float4(0.f, 0.f, 0.f, 0.f);

    // Warp 0: start = lower_bound(memb, chunk0), 32-ary ballot search.
    if (wid == 0) {
        int lo = 0, len = n_atoms;
        while (len > 32) {
            int stride = (len + 31) >> 5;
            bool inwin = (lane * stride) < len;
            bool pred = inwin && (__ldg(memb + lo + lane * stride) < chunk0);
            int cnt = __popc(__ballot_sync(FULL, pred));
            int nprobe = min(32, (len + stride - 1) / stride);
            int newlo = (cnt == 0) ? lo : lo + (cnt - 1) * stride + 1;
            int newhi = (cnt == nprobe) ? lo + len : lo + cnt * stride;
            lo = newlo;
            len = newhi - newlo;
        }
        bool pred = (lane < len) && (__ldg(memb + lo + lane) < chunk0);
        lo += __popc(__ballot_sync(FULL, pred));
        if (lane == 0) s_start = lo;
    }
    __syncthreads();
    const int start = s_start;

    // Stream the chunk's rows: warp w takes 32-row batches at stride 8.
    for (int k = 0; ; ++k) {
        const int row0 = start + (wid + 8 * k) * 32;
        if (row0 >= n_atoms) break;

        const int idx = row0 + lane;
        const int m = (idx < n_atoms) ? memb[idx] : INT_MAX;
        const bool valid = (m < chunk_end);
        const int cnt = __popc(__ballot_sync(FULL, valid)); // prefix (sorted)
        if (cnt == 0) break;

        const float4* base = feats + (size_t)row0 * FEAT4 + lane;
        const float4 z = make_float4(0.f, 0.f, 0.f, 0.f);

        float4 acc = z;
        int cur = __shfl_sync(FULL, m, 0);

        for (int bt = 0; bt * 8 < cnt; ++bt) {
            // 8 independent 128-bit loads, front-batched (MLP_p1 = 8).
            float4 v[8];
            #pragma unroll
            for (int i = 0; i < 8; ++i) {
                int r = bt * 8 + i;
                v[i] = (r < cnt) ? __ldcs(base + (size_t)r * FEAT4) : z;
            }
            #pragma unroll
            for (int i = 0; i < 8; ++i) {
                int r = bt * 8 + i;
                if (r < cnt) {                       // warp-uniform branch
                    int mm = __shfl_sync(FULL, m, r);
                    if (mm != cur) {                 // rare: ~1 per batch
                        float* s = s_acc[cur - chunk0];
                        atomicAdd(s + lane * 4 + 0, acc.x);
                        atomicAdd(s + lane * 4 + 1, acc.y);
                        atomicAdd(s + lane * 4 + 2, acc.z);
                        atomicAdd(s + lane * 4 + 3, acc.w);
                        acc = z;
                        cur = mm;
                    }
                }
                acc.x += v[i].x; acc.y += v[i].y;    // v[i]=0 past cnt
                acc.z += v[i].z; acc.w += v[i].w;
            }
        }
        {   // end-of-batch flush (carry cannot cross strided batches)
            float* s = s_acc[cur - chunk0];
            atomicAdd(s + lane * 4 + 0, acc.x);
            atomicAdd(s + lane * 4 + 1, acc.y);
            atomicAdd(s + lane * 4 + 2, acc.z);
            atomicAdd(s + lane * 4 + 3, acc.w);
        }
        if (cnt < 32) break;                         // chunk exhausted
    }

    __syncthreads();

    // Write out 8 segments x 128 floats: thread t -> seg t/32, float4 col t%32.
    const int seg = chunk0 + (tid >> 5);
    if (seg < chunk_end) {
        float4 val = ((float4*)s_acc)[tid];
        out[(size_t)seg * FEAT4 + (tid & 31)] = val;
    }
}

extern "C" void kernel_launch(void* const* d_in, const int* in_sizes, int n_in,
                              void* d_out, int out_size) {
    const float* feats = (const float*)d_in[0];
    const int* memb = (const int*)d_in[1];
    float* out = (float*)d_out;

    const int n_atoms = in_sizes[1];          // 524288
    const int batch = out_size / N_FEAT;      // 16384

    const int blocks = (batch + SEGS - 1) / SEGS;   // 2048
    gg_fused_kernel<<<blocks, TPB>>>((const float4*)feats, memb,
                                     (float4*)out, n_atoms, batch);
}

// round 14
// speedup vs baseline: 1.0293x; 1.0293x over previous
#include <cuda_runtime.h>
#include <cuda_bf16.h>

// GraphGather / segment_sum — single kernel, no init pass, no atomics:
//   out[b, :] = sum of feats[a, :] for membership[a] == b
// feats: [524288, 128] f32, membership: [524288] i32 (SORTED), out: [16384, 128] f32.
//
// R14: ownership-by-segment-start on the R6 streamer shape.
//  - warp owns rows [32w, 32w+32). Leading rows continuing the previous
//    warp's segment are SKIPPED (features untouched; their owner reads them).
//  - every segment STARTING in range is fully summed (extension past the
//    range end via ballot-bounded predicated 8-deep float4 batches) and
//    written once with a plain STG.128.
//  - empty-segment gaps are zero-stored by the warp owning the gap's right
//    edge; trailing empties by the warp whose segment ends at n_atoms.
//  => every feats row read exactly once, every out row written exactly once
//     (poison overwritten), no atomics, no zero pass, replay-idempotent,
//     exact row-order accumulation (rel_err = 0).

#define N_FEAT 128
#define FEAT4 (N_FEAT / 4)     // 32 float4 per row
#define TPB 256

__global__ __launch_bounds__(TPB)
void gg_kernel(const float4* __restrict__ feats,
               const int* __restrict__ memb,
               float4* __restrict__ out,
               int n_atoms, int batch) {
    const int warp_id = (blockIdx.x * TPB + threadIdx.x) >> 5;
    const int lane = threadIdx.x & 31;
    const unsigned FULL = 0xFFFFFFFFu;
    const float4 z = make_float4(0.f, 0.f, 0.f, 0.f);

    const int row0 = warp_id * 32;
    if (row0 >= n_atoms) return;

    // Memberships for the owned range (coalesced; sentinel past the end).
    const int idx = row0 + lane;
    const int m = (idx < n_atoms) ? memb[idx] : batch;
    const int prev = (row0 == 0) ? -1 : __ldg(memb + row0 - 1);

    // Leading rows continuing prev's segment are skipped (owner reads them).
    const unsigned contb = __ballot_sync(FULL, m == prev);
    const int skip = (~contb == 0u) ? 32 : (__ffs(~contb) - 1);

    float4 acc = z;
    int cur = -1;
    bool closed = false;   // set when cur hit the sentinel (range tail OOB)

    if (skip < 32) {
        const float4* base = feats + (size_t)row0 * FEAT4 + lane;

        #pragma unroll
        for (int bt = 0; bt < 4; ++bt) {
            // 8 independent 128-bit loads, front-batched (MLP_p1 = 8).
            float4 v[8];
            #pragma unroll
            for (int i = 0; i < 8; ++i) {
                int r = bt * 8 + i;
                bool ld = (r >= skip) && (row0 + r < n_atoms);
                v[i] = ld ? __ldcs(base + (size_t)r * FEAT4) : z;
            }

            #pragma unroll
            for (int i = 0; i < 8; ++i) {
                int r = bt * 8 + i;
                if (r >= skip && !closed) {          // warp-uniform
                    int mm = __shfl_sync(FULL, m, r);
                    if (r == skip) {
                        // gap (prev, mm): zero-store empty segments
                        for (int s = prev + 1; s < mm; ++s)
                            out[(size_t)s * FEAT4 + lane] = z;
                        cur = mm;
                    } else if (mm != cur) {
                        out[(size_t)cur * FEAT4 + lane] = acc;  // complete
                        int gend = mm < batch ? mm : batch;
                        for (int s = cur + 1; s < gend; ++s)
                            out[(size_t)s * FEAT4 + lane] = z;
                        acc = z;
                        cur = mm;
                        if (mm >= batch) closed = true;  // sentinel: done
                    }
                }
                acc.x += v[i].x; acc.y += v[i].y;    // v[i]=0 when skipped
                acc.z += v[i].z; acc.w += v[i].w;
            }
        }

        // Extension: finish the last segment that started in range.
        if (!closed) {
            int j = row0 + 32;
            while (true) {
                int id2 = j + lane;
                int me = (id2 < n_atoms) ? __ldg(memb + id2) : batch;
                unsigned diff = __ballot_sync(FULL, me != cur);
                int cnt = diff ? (__ffs(diff) - 1) : 32;   // prefix == cur

                if (cnt > 0) {
                    const float4* b2 = feats + (size_t)j * FEAT4 + lane;
                    for (int bt = 0; bt * 8 < cnt; ++bt) {
                        float4 v[8];
                        #pragma unroll
                        for (int i = 0; i < 8; ++i) {
                            int r = bt * 8 + i;
                            v[i] = (r < cnt) ? __ldcs(b2 + (size_t)r * FEAT4)
                                             : z;
                        }
                        #pragma unroll
                        for (int i = 0; i < 8; ++i) {
                            acc.x += v[i].x; acc.y += v[i].y;
                            acc.z += v[i].z; acc.w += v[i].w;
                        }
                    }
                }

                if (cnt < 32) {
                    out[(size_t)cur * FEAT4 + lane] = acc;   // complete
                    int bval = __shfl_sync(FULL, me, cnt);
                    if (bval >= batch) {
                        // segment ended at n_atoms: zero trailing empties
                        for (int s = cur + 1; s < batch; ++s)
                            out[(size_t)s * FEAT4 + lane] = z;
                    }
                    // else: warp owning row (j+cnt) zero-stores the gap.
                    break;
                }
                j += 32;
            }
        }
    }
}

extern "C" void kernel_launch(void* const* d_in, const int* in_sizes, int n_in,
                              void* d_out, int out_size) {
    const float* feats = (const float*)d_in[0];
    const int* memb = (const int*)d_in[1];
    float* out = (float*)d_out;

    const int n_atoms = in_sizes[1];          // 524288
    const int batch = out_size / N_FEAT;      // 16384

    const int n_warps = (n_atoms + 31) / 32;  // 16384
    const int blocks = (n_warps + (TPB / 32) - 1) / (TPB / 32);   // 2048
    gg_kernel<<<blocks, TPB>>>((const float4*)feats, memb,
                               (float4*)out, n_atoms, batch);
}

// round 15
// speedup vs baseline: 1.1195x; 1.0876x over previous
#include <cuda_runtime.h>
#include <cuda_bf16.h>

// GraphGather / segment_sum:
//   out[b, :] = sum of feats[a, :] for membership[a] == b
// feats: [524288, 128] f32, membership: [524288] i32 (SORTED), out: [16384, 128] f32.
//
// R15 = R7 (memset node + R6 streamer, best segsum 44.2us @81% DRAM) with
// TPB=128: at regs~54 this packs 9 blocks/SM = 36 resident warps (vs 32 at
// TPB=256), raising in-flight read sectors ~12% -> higher achieved HBM BW.
// ROWS_PER_WARP stays 32 and the loop body is identical to R6 (the proven
// configuration; R4's TPB=128 regression was caused by ROWS=64, not TPB).
//  - one coalesced membership load per warp, shfl-distributed
//  - 4 batches of 8 unconditional LDG.E.128 (MLP_p1 = 8), evict-first
//  - boundary flushes via red.global.add.v4.f32 (one 16B RMW per lane)
//  - output zeroed by a cudaMemsetAsync graph node (f32 0.0 == 0x0 bytes)

#define N_FEAT 128
#define FEAT4 (N_FEAT / 4)       // 32 float4 per row
#define ROWS_PER_WARP 32
#define TPB 128

__device__ __forceinline__ void gg_flush(float* __restrict__ out,
                                         int seg, int lane, const float4& acc) {
    // byte offset = seg*512 + lane*16 -> 16B aligned.
    float* o = out + (size_t)seg * N_FEAT + lane * 4;
    asm volatile("red.global.add.v4.f32 [%0], {%1, %2, %3, %4};"
                 :: "l"(o), "f"(acc.x), "f"(acc.y), "f"(acc.z), "f"(acc.w)
                 : "memory");
}

__global__ __launch_bounds__(TPB)
void gg_segsum_kernel(const float4* __restrict__ feats,
                      const int* __restrict__ memb,
                      float* __restrict__ out,
                      int n_atoms) {
    const int warp_id = (blockIdx.x * TPB + threadIdx.x) >> 5;
    const int lane = threadIdx.x & 31;
    const unsigned FULL = 0xFFFFFFFFu;

    const int row0 = warp_id * ROWS_PER_WARP;
    if (row0 >= n_atoms) return;

    // One coalesced membership load for the warp's 32 rows.
    const int last = n_atoms - 1;
    int mrow = row0 + lane;
    int mlane = memb[mrow <= last ? mrow : last];

    const int nrows = (row0 + ROWS_PER_WARP <= n_atoms) ? ROWS_PER_WARP
                                                        : (n_atoms - row0);
    const float4* base = feats + (size_t)row0 * FEAT4 + lane;

    float4 acc = make_float4(0.f, 0.f, 0.f, 0.f);
    int cur = __shfl_sync(FULL, mlane, 0);

    if (nrows == ROWS_PER_WARP) {
        #pragma unroll
        for (int bt = 0; bt < 4; ++bt) {
            // 8 independent 128-bit loads, issued back-to-back (MLP_p1 = 8).
            float4 v[8];
            #pragma unroll
            for (int i = 0; i < 8; ++i)
                v[i] = __ldcs(base + (size_t)(bt * 8 + i) * FEAT4);

            #pragma unroll
            for (int i = 0; i < 8; ++i) {
                int m = __shfl_sync(FULL, mlane, bt * 8 + i);
                if (m != cur) {            // rare: ~1 boundary / warp
                    gg_flush(out, cur, lane, acc);
                    acc = make_float4(0.f, 0.f, 0.f, 0.f);
                    cur = m;
                }
                acc.x += v[i].x; acc.y += v[i].y;
                acc.z += v[i].z; acc.w += v[i].w;
            }
        }
    } else {
        for (int i = 0; i < nrows; ++i) {
            float4 v = __ldcs(base + (size_t)i * FEAT4);
            int m = __shfl_sync(FULL, mlane, i);
            if (m != cur) {
                gg_flush(out, cur, lane, acc);
                acc = make_float4(0.f, 0.f, 0.f, 0.f);
                cur = m;
            }
            acc.x += v.x; acc.y += v.y; acc.z += v.z; acc.w += v.w;
        }
    }

    gg_flush(out, cur, lane, acc);
}

extern "C" void kernel_launch(void* const* d_in, const int* in_sizes, int n_in,
                              void* d_out, int out_size) {
    const float* feats = (const float*)d_in[0];
    const int* memb = (const int*)d_in[1];
    float* out = (float*)d_out;

    const int n_atoms = in_sizes[1];      // 524288

    // Zero the poisoned output via a graph memset node (f32 0.0 == 0x00000000).
    cudaMemsetAsync(out, 0, (size_t)out_size * sizeof(float));

    const int n_warps = (n_atoms + ROWS_PER_WARP - 1) / ROWS_PER_WARP;
    const int blocks = (n_warps + (TPB / 32) - 1) / (TPB / 32);   // 4096
    gg_segsum_kernel<<<blocks, TPB>>>((const float4*)feats, memb, out, n_atoms);
}

// round 16
// speedup vs baseline: 1.1287x; 1.0082x over previous
#include <cuda_runtime.h>
#include <cuda_bf16.h>

// GraphGather / segment_sum:
//   out[b, :] = sum of feats[a, :] for membership[a] == b
// feats: [524288, 128] f32, membership: [524288] i32 (SORTED), out: [16384, 128] f32.
//
// R16: consolidation of per-component winners across 15 measured rounds.
//  - geometry: TPB=256, ROWS_PER_WARP=32, grid 2048 (best totals: R3/R6/R7)
//  - prologue: float4 zero-fill kernel (R3, best measured total)
//  - flush: red.global.add.v4.f32 (fastest segsum body per ncu: 44.2us)
//  - body: 4 batches of 8 unconditional LDG.E.128 (MLP_p1=8, evict-first)
//  - NEW: uniform-warp fast path (~37% of warps have no segment boundary
//    in their 32 rows): one ballot detects it, then a branch/shfl-free
//    accumulate loop + single flush. No extra memory work, same registers.

#define N_FEAT 128
#define FEAT4 (N_FEAT / 4)       // 32 float4 per row
#define ROWS_PER_WARP 32
#define TPB 256

__global__ __launch_bounds__(TPB)
void gg_zero4_kernel(float4* __restrict__ out, int n4) {
    int i = blockIdx.x * blockDim.x + threadIdx.x;
    if (i < n4) out[i] = make_float4(0.f, 0.f, 0.f, 0.f);
}

__device__ __forceinline__ void gg_flush(float* __restrict__ out,
                                         int seg, int lane, const float4& acc) {
    // byte offset = seg*512 + lane*16 -> 16B aligned.
    float* o = out + (size_t)seg * N_FEAT + lane * 4;
    asm volatile("red.global.add.v4.f32 [%0], {%1, %2, %3, %4};"
                 :: "l"(o), "f"(acc.x), "f"(acc.y), "f"(acc.z), "f"(acc.w)
                 : "memory");
}

__global__ __launch_bounds__(TPB)
void gg_segsum_kernel(const float4* __restrict__ feats,
                      const int* __restrict__ memb,
                      float* __restrict__ out,
                      int n_atoms) {
    const int warp_id = (blockIdx.x * TPB + threadIdx.x) >> 5;
    const int lane = threadIdx.x & 31;
    const unsigned FULL = 0xFFFFFFFFu;

    const int row0 = warp_id * ROWS_PER_WARP;
    if (row0 >= n_atoms) return;

    // One coalesced membership load for the warp's 32 rows.
    const int last = n_atoms - 1;
    int mrow = row0 + lane;
    int mlane = memb[mrow <= last ? mrow : last];

    const int nrows = (row0 + ROWS_PER_WARP <= n_atoms) ? ROWS_PER_WARP
                                                        : (n_atoms - row0);
    const float4* base = feats + (size_t)row0 * FEAT4 + lane;

    float4 acc = make_float4(0.f, 0.f, 0.f, 0.f);
    int cur = __shfl_sync(FULL, mlane, 0);

    // Uniform-warp detection: no boundary in this warp's 32 rows (~37%).
    const bool uniform = (__ballot_sync(FULL, mlane == cur) == FULL);

    if (nrows == ROWS_PER_WARP) {
        if (uniform) {
            // Fast path: no shfl, no branches — pure streaming accumulate.
            #pragma unroll
            for (int bt = 0; bt < 4; ++bt) {
                float4 v[8];
                #pragma unroll
                for (int i = 0; i < 8; ++i)
                    v[i] = __ldcs(base + (size_t)(bt * 8 + i) * FEAT4);
                #pragma unroll
                for (int i = 0; i < 8; ++i) {
                    acc.x += v[i].x; acc.y += v[i].y;
                    acc.z += v[i].z; acc.w += v[i].w;
                }
            }
        } else {
            #pragma unroll
            for (int bt = 0; bt < 4; ++bt) {
                // 8 independent 128-bit loads, back-to-back (MLP_p1 = 8).
                float4 v[8];
                #pragma unroll
                for (int i = 0; i < 8; ++i)
                    v[i] = __ldcs(base + (size_t)(bt * 8 + i) * FEAT4);

                #pragma unroll
                for (int i = 0; i < 8; ++i) {
                    int m = __shfl_sync(FULL, mlane, bt * 8 + i);
                    if (m != cur) {        // ~1 boundary / warp
                        gg_flush(out, cur, lane, acc);
                        acc = make_float4(0.f, 0.f, 0.f, 0.f);
                        cur = m;
                    }
                    acc.x += v[i].x; acc.y += v[i].y;
                    acc.z += v[i].z; acc.w += v[i].w;
                }
            }
        }
    } else {
        for (int i = 0; i < nrows; ++i) {
            float4 v = __ldcs(base + (size_t)i * FEAT4);
            int m = __shfl_sync(FULL, mlane, i);
            if (m != cur) {
                gg_flush(out, cur, lane, acc);
                acc = make_float4(0.f, 0.f, 0.f, 0.f);
                cur = m;
            }
            acc.x += v.x; acc.y += v.y; acc.z += v.z; acc.w += v.w;
        }
    }

    gg_flush(out, cur, lane, acc);
}

extern "C" void kernel_launch(void* const* d_in, const int* in_sizes, int n_in,
                              void* d_out, int out_size) {
    const float* feats = (const float*)d_in[0];
    const int* memb = (const int*)d_in[1];
    float* out = (float*)d_out;

    const int n_atoms = in_sizes[1];      // 524288
    const int n4 = out_size / 4;          // 524288 float4

    gg_zero4_kernel<<<(n4 + 255) / 256, 256>>>((float4*)out, n4);

    const int n_warps = (n_atoms + ROWS_PER_WARP - 1) / ROWS_PER_WARP;
    const int blocks = (n_warps + (TPB / 32) - 1) / (TPB / 32);
    gg_segsum_kernel<<<blocks, TPB>>>((const float4*)feats, memb, out, n_atoms);
}